// round 17
// baseline (speedup 1.0000x reference)
#include <cuda_runtime.h>
#include <cstdint>

typedef unsigned long long ull;

#define NB 128
#define NT 4096
#define NTH 128
#define NCHUNK 8            // CTAs per batch; 32 warps per batch
#define TOKC 512            // tokens per CTA (4 per thread)

__device__ float g_scratch[NB * 32 * 17];   // per-WARP slots: [b][warp0..31][sum, ctx16]
__device__ int   g_cnt1[NB];                // sum-ready arrivals (32 per batch)
__device__ int   g_cnt2[NB];                // done arrivals (32 per batch)

__constant__ ulonglong2 cW2q[32 * 4];       // W2 rows as 128-bit packed quads

__device__ __forceinline__ float ex2f_(float x) {
    float y; asm("ex2.approx.f32 %0, %1;" : "=f"(y) : "f"(x)); return y;
}
__device__ __forceinline__ float rcpf_(float x) {
    float y; asm("rcp.approx.f32 %0, %1;" : "=f"(y) : "f"(x)); return y;
}
__device__ __forceinline__ float tanhf_(float x) {
    float y; asm("tanh.approx.f32 %0, %1;" : "=f"(y) : "f"(x)); return y;
}
__device__ __forceinline__ void pfma(ull& d, ull a, ull b) {
    asm("fma.rn.f32x2 %0, %1, %2, %0;" : "+l"(d) : "l"(a), "l"(b));
}
__device__ __forceinline__ ull pack2(float a, float b) {
    ull p; asm("mov.b64 %0, {%1, %2};" : "=l"(p) : "f"(a), "f"(b)); return p;
}
__device__ __forceinline__ float2 unpack2(ull p) {
    float2 r; asm("mov.b64 {%0, %1}, %2;" : "=f"(r.x), "=f"(r.y) : "l"(p)); return r;
}
__device__ __forceinline__ void red_release_add(int* p, int v) {
    asm volatile("red.release.gpu.global.add.s32 [%0], %1;" :: "l"(p), "r"(v) : "memory");
}
__device__ __forceinline__ int ld_acquire(const int* p) {
    int v; asm volatile("ld.acquire.gpu.global.s32 %0, [%1];" : "=r"(v) : "l"(p) : "memory");
    return v;
}
__device__ __forceinline__ float ldaf(const float* p) {
    float v; asm volatile("ld.acquire.gpu.global.f32 %0, [%1];" : "=f"(v) : "l"(p) : "memory");
    return v;
}
__device__ __forceinline__ int atom_add_acqrel(int* p, int v) {
    int old;
    asm volatile("atom.acq_rel.gpu.global.add.s32 %0, [%1], %2;"
                 : "=r"(old) : "l"(p), "r"(v) : "memory");
    return old;
}
__device__ __forceinline__ uint32_t s2u(const void* p) {
    uint32_t a;
    asm("{ .reg .u64 t; cvta.to.shared.u64 t, %1; cvt.u32.u64 %0, t; }"
        : "=r"(a) : "l"(p));
    return a;
}
__device__ __forceinline__ void cp16(uint32_t dst, const void* g) {
    asm volatile("cp.async.cg.shared.global [%0], [%1], 16;" :: "r"(dst), "l"(g));
}
__device__ __forceinline__ void cpcommit() {
    asm volatile("cp.async.commit_group;");
}
__device__ __forceinline__ void cpwait0() {
    asm volatile("cp.async.wait_group 0;");
}

// swizzled offset of (token, quarter) inside a 64-token x 64B tile buffer
__device__ __forceinline__ uint32_t qoff(int t, int q) {
    return (uint32_t)(t * 64 + ((q ^ ((t >> 1) & 3)) * 16));
}

__device__ __forceinline__ void stage_tile(uint32_t sw, const float* gsrc, int lane) {
    #pragma unroll
    for (int k = 0; k < 8; k++) {
        const int c = lane + k * 32;
        cp16(sw + qoff(c >> 2, c & 3), gsrc + (size_t)c * 4);
    }
    cpcommit();
}

__device__ __forceinline__ void read_pair(const char* buf, int lane, ull* ka, ull* kb) {
    #pragma unroll
    for (int q = 0; q < 4; q++) {
        ulonglong2 va = *reinterpret_cast<const ulonglong2*>(buf + qoff(lane, q));
        ka[2*q] = va.x; ka[2*q+1] = va.y;
        ulonglong2 vb_ = *reinterpret_cast<const ulonglong2*>(buf + qoff(lane + 32, q));
        kb[2*q] = vb_.x; kb[2*q+1] = vb_.y;
    }
}

__global__ void __launch_bounds__(NTH, 8)
attn_fused(const float* __restrict__ query,   // [B,1,16]
           const float* __restrict__ key,     // [B,T,16]
           const float* __restrict__ value,   // [B,T,16]
           const float* __restrict__ W1,      // [32,16]
           const float* __restrict__ bias,    // scalar
           const float* __restrict__ v_w,     // [1,32]
           const float* __restrict__ v_b,     // [1]
           float* __restrict__ out_ctx,       // [B,16]
           float* __restrict__ out_attn)      // [B,T]
{
    const int cta   = blockIdx.x;
    const int b     = cta >> 3;
    const int chunk = cta & 7;
    const int base  = chunk * TOKC;
    const int tid   = threadIdx.x;
    const int lane  = tid & 31;
    const int wid   = tid >> 5;
    const int gw    = (chunk << 2) | wid;        // warp index within batch: 0..31

    __shared__ __align__(16) char swz[4][4096];  // per-warp staging buffers
    __shared__ ulonglong2 scv[32];   // .x=(qproj+bias, 0), .y lo = L*v_w[w]

    const uint32_t sw   = s2u(swz[wid]);
    const char*    bufc = swz[wid];

    const int tile0 = base + wid * 64;
    const int tile1 = base + wid * 64 + 256;
    const float* krow = key   + (size_t)b * NT * 16;
    const float* vrow = value + (size_t)b * NT * 16;
    const float L = 1.4426950408889634f;

    // G1: key tile 0 — issue immediately
    stage_tile(sw, krow + (size_t)tile0 * 16, lane);

    // prologue: q projection + v_w staging (overlaps K0 flight)
    if (tid < 32) {
        const int w = tid;
        float acc = *bias;
        #pragma unroll
        for (int d = 0; d < 16; d++)
            acc = fmaf(query[b * 16 + d], W1[w * 16 + d], acc);
        scv[w].x = pack2(acc, 0.0f);
        scv[w].y = pack2(L * v_w[w], 0.0f);
    }
    __syncthreads();      // the ONLY CTA-wide barrier in the kernel

    const float vbL = v_b[0] * L;

    // ---------- Scores + inline exp (no max pass: bounded scores) ----------
    float e_[4];
    float csum = 0.0f;

    #pragma unroll
    for (int jp = 0; jp < 2; jp++) {
        cpwait0();
        __syncwarp();
        ull ka[8], kb[8];
        read_pair(bufc, lane, ka, kb);
        __syncwarp();

        if (jp == 0)
            stage_tile(sw, krow + (size_t)tile1 * 16, lane);   // G2: key tile 1
        else
            stage_tile(sw, vrow + (size_t)tile0 * 16, lane);   // G3: value tile A

        float a0 = vbL, a1 = vbL;
        #pragma unroll 4
        for (int w = 0; w < 32; w++) {
            const ulonglong2 cc = scv[w];
            ull acc0 = cc.x;
            ull acc1 = acc0;
            const float vwL = unpack2(cc.y).x;
            const ulonglong2* wr = &cW2q[w * 4];
            ulonglong2 w01 = wr[0];
            pfma(acc0, ka[0], w01.x); pfma(acc1, kb[0], w01.x);
            pfma(acc0, ka[1], w01.y); pfma(acc1, kb[1], w01.y);
            ulonglong2 w23 = wr[1];
            pfma(acc0, ka[2], w23.x); pfma(acc1, kb[2], w23.x);
            pfma(acc0, ka[3], w23.y); pfma(acc1, kb[3], w23.y);
            ulonglong2 w45 = wr[2];
            pfma(acc0, ka[4], w45.x); pfma(acc1, kb[4], w45.x);
            pfma(acc0, ka[5], w45.y); pfma(acc1, kb[5], w45.y);
            ulonglong2 w67 = wr[3];
            pfma(acc0, ka[6], w67.x); pfma(acc1, kb[6], w67.x);
            pfma(acc0, ka[7], w67.y); pfma(acc1, kb[7], w67.y);

            const float2 h0 = unpack2(acc0);
            const float2 h1 = unpack2(acc1);
            const float t0h = tanhf_(h0.x + h0.y);
            const float t1h = tanhf_(h1.x + h1.y);
            a0 = fmaf(vwL, t0h, a0);
            a1 = fmaf(vwL, t1h, a1);
        }
        const float e0 = ex2f_(a0);
        const float e1 = ex2f_(a1);
        e_[2 * jp + 0] = e0;
        e_[2 * jp + 1] = e1;
        csum += e0 + e1;
    }

    // ---------- Value accumulation (two tiles, per-warp pipelined) ----------
    ull cv[8];
    #pragma unroll
    for (int i = 0; i < 8; i++) cv[i] = 0ull;

    {   // value tile A
        cpwait0();
        __syncwarp();
        ull va[8], vbr[8];
        read_pair(bufc, lane, va, vbr);
        __syncwarp();
        stage_tile(sw, vrow + (size_t)tile1 * 16, lane);       // G4: value tile B

        const ull ee0 = pack2(e_[0], e_[0]);
        const ull ee1 = pack2(e_[1], e_[1]);
        #pragma unroll
        for (int i = 0; i < 8; i++) {
            pfma(cv[i], ee0, va[i]);
            pfma(cv[i], ee1, vbr[i]);
        }
    }
    {   // value tile B
        cpwait0();
        __syncwarp();
        ull va[8], vbr[8];
        read_pair(bufc, lane, va, vbr);

        const ull ee2 = pack2(e_[2], e_[2]);
        const ull ee3 = pack2(e_[3], e_[3]);
        #pragma unroll
        for (int i = 0; i < 8; i++) {
            pfma(cv[i], ee2, va[i]);
            pfma(cv[i], ee3, vbr[i]);
        }
    }

    float cvf[16];
    #pragma unroll
    for (int i = 0; i < 8; i++) {
        float2 u = unpack2(cv[i]);
        cvf[2*i] = u.x; cvf[2*i+1] = u.y;
    }

    // ---------- Per-warp shfl reductions (no smem, no CTA barrier) ----------
    #pragma unroll
    for (int o = 16; o > 0; o >>= 1) {
        csum += __shfl_xor_sync(0xffffffffu, csum, o);
        #pragma unroll
        for (int i = 0; i < 16; i++)
            cvf[i] += __shfl_xor_sync(0xffffffffu, cvf[i], o);
    }

    // ---------- Publish this WARP's partial; arrive; spin ----------
    float* slot = g_scratch + ((size_t)(b << 5) | gw) * 17;
    if (lane == 0) {
        slot[0] = csum;
        #pragma unroll
        for (int i = 0; i < 16; i++) slot[1 + i] = cvf[i];
        red_release_add(&g_cnt1[b], 1);
        while (ld_acquire(&g_cnt1[b]) < 32) __nanosleep(32);
    }
    __syncwarp();

    // all lanes: acquire-load the 32 warp sums; deterministic xor-tree total
    float total = ldaf(g_scratch + ((size_t)(b << 5) | lane) * 17);
    #pragma unroll
    for (int o = 16; o > 0; o >>= 1)
        total += __shfl_xor_sync(0xffffffffu, total, o);
    const float inv = rcpf_(total);

    float* ao = out_attn + (size_t)b * NT;
    ao[tile0 + lane]      = e_[0] * inv;
    ao[tile0 + lane + 32] = e_[1] * inv;
    ao[tile1 + lane]      = e_[2] * inv;
    ao[tile1 + lane + 32] = e_[3] * inv;

    // ---------- Last-arriving WARP writes ctx + resets ----------
    int lastf = 0;
    if (lane == 0)
        lastf = (atom_add_acqrel(&g_cnt2[b], 1) == 31);
    lastf = __shfl_sync(0xffffffffu, lastf, 0);
    if (lastf) {
        if (lane < 16) {
            const float* gs = g_scratch + (size_t)(b << 5) * 17;
            float acc = 0.0f;
            #pragma unroll
            for (int c = 0; c < 32; c++)
                acc += ldaf(gs + c * 17 + 1 + lane);     // fixed order
            out_ctx[b * 16 + lane] = acc * inv;
        }
        __syncwarp();
        if (lane == 0) {       // all 32 warps already passed both counters
            g_cnt1[b] = 0;
            __threadfence();
            g_cnt2[b] = 0;
        }
    }
}

extern "C" void kernel_launch(void* const* d_in, const int* in_sizes, int n_in,
                              void* d_out, int out_size) {
    const float* query = (const float*)d_in[0];
    const float* key   = (const float*)d_in[1];
    const float* value = (const float*)d_in[2];
    const float* W1    = (const float*)d_in[3];
    const float* W2    = (const float*)d_in[4];
    const float* bias  = (const float*)d_in[5];
    const float* v_w   = (const float*)d_in[6];
    const float* v_b   = (const float*)d_in[7];

    float* out_ctx  = (float*)d_out;            // [B,1,16]
    float* out_attn = (float*)d_out + NB * 16;  // [B,T]

    cudaMemcpyToSymbolAsync(cW2q, W2, 32 * 16 * sizeof(float), 0,
                            cudaMemcpyDeviceToDevice);

    attn_fused<<<NB * NCHUNK, NTH>>>(query, key, value, W1,
                                     bias, v_w, v_b, out_ctx, out_attn);
}